// round 13
// baseline (speedup 1.0000x reference)
#include <cuda_runtime.h>

#define Pl  (128*128)
#define V   (128*128*128)
#define PX  136
#define PPl (130*136)
#define PV  (130*130*136)

typedef unsigned long long u64;

__device__ __forceinline__ u64 pk(float lo, float hi) {
    u64 r; asm("mov.b64 %0,{%1,%2};" : "=l"(r) : "f"(lo), "f"(hi)); return r;
}
__device__ __forceinline__ void fma2(u64 &d, u64 a, u64 b) {
    asm("fma.rn.f32x2 %0,%1,%2,%0;" : "+l"(d) : "l"(a), "l"(b));
}
__device__ __forceinline__ u64 mul2(u64 a, u64 b) {
    u64 r; asm("mul.rn.f32x2 %0,%1,%2;" : "=l"(r) : "l"(a), "l"(b)); return r;
}
__device__ __forceinline__ u64 add2(u64 a, u64 b) {
    u64 r; asm("add.rn.f32x2 %0,%1,%2;" : "=l"(r) : "l"(a), "l"(b)); return r;
}
__device__ __forceinline__ u64 abs2(u64 a) { return a & 0x7FFFFFFF7FFFFFFFULL; }
__device__ __forceinline__ float2 upk(u64 a) {
    float2 f; asm("mov.b64 {%0,%1},%2;" : "=f"(f.x), "=f"(f.y) : "l"(a)); return f;
}

// Padded scratch: [8][130][130][136], data voxel (z,y,x) at (z+1, y+1, x+4).
__device__ float g_xp[8 * PV];
__device__ float g_hp[8 * PV];
__device__ float g_tp[8 * PV];
__device__ float g_w [27 * V];   // unnormalized conv2 output (flat)

// ---------------------------------------------------------------------------
// pad_x: copy x into g_xp interior, zero g_xp halo
// ---------------------------------------------------------------------------
__global__ __launch_bounds__(160) void k_pad_x(const float* __restrict__ x)
{
    int row = blockIdx.x;                 // 8*130*130 rows
    int xx  = threadIdx.x;
    if (xx >= PX) return;
    int c   = row / (130 * 130);
    int rem = row % (130 * 130);
    int zz  = rem / 130;
    int yy  = rem % 130;
    bool halo = (zz == 0) | (zz == 129) | (yy == 0) | (yy == 129) | (xx < 4) | (xx >= 132);
    float v = 0.f;
    if (!halo)
        v = x[(size_t)c * V + (size_t)(zz - 1) * Pl + (yy - 1) * 128 + (xx - 4)];
    g_xp[(size_t)c * PV + zz * PPl + yy * PX + xx] = v;
}

// ---------------------------------------------------------------------------
// halo zeroing, one buffer each (also splits launches so conv1 lands in the
// profiled slot #4)
// ---------------------------------------------------------------------------
__global__ __launch_bounds__(160) void k_halo_h()
{
    int row = blockIdx.x;
    int xx  = threadIdx.x;
    if (xx >= PX) return;
    int c   = row / (130 * 130);
    int rem = row % (130 * 130);
    int zz  = rem / 130;
    int yy  = rem % 130;
    bool halo = (zz == 0) | (zz == 129) | (yy == 0) | (yy == 129) | (xx < 4) | (xx >= 132);
    if (halo) g_hp[(size_t)c * PV + zz * PPl + yy * PX + xx] = 0.f;
}
__global__ __launch_bounds__(160) void k_halo_t()
{
    int row = blockIdx.x;
    int xx  = threadIdx.x;
    if (xx >= PX) return;
    int c   = row / (130 * 130);
    int rem = row % (130 * 130);
    int zz  = rem / 130;
    int yy  = rem % 130;
    bool halo = (zz == 0) | (zz == 129) | (yy == 0) | (yy == 129) | (xx < 4) | (xx >= 132);
    if (halo) g_tp[(size_t)c * PV + zz * PPl + yy * PX + xx] = 0.f;
}

// ---------------------------------------------------------------------------
// conv1: g_xp -> g_hp = relu(conv3x3x3(x, w1) + b1), 8->8 channels.
// f32x2 lanes = (oc_even, oc_odd); inputs duplicated; 4 x per thread.
// Weight taps load as 2x LDS.128 per s-group (32B-aligned ws layout).
// ---------------------------------------------------------------------------
__global__ __launch_bounds__(256, 4) void k_conv1(const float* __restrict__ w1,
                                                  const float* __restrict__ b1)
{
    __shared__ float2 ws[8 * 27 * 4];   // [ic][tap][pair], tap group = 32B aligned
    __shared__ float2 bs[4];
    int tid = threadIdx.y * 32 + threadIdx.x;
    for (int i = tid; i < 864; i += 256) {
        int p = i & 3; int it = i >> 2; int t = it % 27; int ic = it / 27;
        ws[i] = make_float2(w1[(2 * p) * 216 + ic * 27 + t],
                            w1[(2 * p + 1) * 216 + ic * 27 + t]);
    }
    if (tid < 4) bs[tid] = make_float2(b1[2 * tid], b1[2 * tid + 1]);
    __syncthreads();

    int x0 = threadIdx.x * 4;
    int y  = blockIdx.x * 8 + threadIdx.y;
    int z  = blockIdx.y;

    u64 acc[4][4];   // [ocpair][x]
    #pragma unroll
    for (int p = 0; p < 4; p++) {
        u64 b = *reinterpret_cast<const u64*>(&bs[p]);
        acc[p][0] = b; acc[p][1] = b; acc[p][2] = b; acc[p][3] = b;
    }

    #pragma unroll 1
    for (int ic = 0; ic < 8; ic++) {
        const float* xc = g_xp + (size_t)ic * PV + (size_t)z * PPl + y * PX + x0 + 3;
        #pragma unroll
        for (int dz = 0; dz < 3; dz++) {
            #pragma unroll
            for (int dy = 0; dy < 3; dy++) {
                const float* r = xc + dz * PPl + dy * PX;
                float  i0 = r[0];
                float4 a4 = *reinterpret_cast<const float4*>(r + 1);
                float  i5 = r[5];
                u64 d[6];
                d[0] = pk(i0,   i0);   d[1] = pk(a4.x, a4.x);
                d[2] = pk(a4.y, a4.y); d[3] = pk(a4.z, a4.z);
                d[4] = pk(a4.w, a4.w); d[5] = pk(i5,   i5);
                const ulonglong2* wq2 =
                    reinterpret_cast<const ulonglong2*>(&ws[(ic * 27 + (dz * 3 + dy) * 3) * 4]);
                #pragma unroll
                for (int s = 0; s < 3; s++) {
                    ulonglong2 wa = wq2[2 * s];
                    ulonglong2 wb = wq2[2 * s + 1];
                    fma2(acc[0][0], d[s + 0], wa.x);
                    fma2(acc[0][1], d[s + 1], wa.x);
                    fma2(acc[0][2], d[s + 2], wa.x);
                    fma2(acc[0][3], d[s + 3], wa.x);
                    fma2(acc[1][0], d[s + 0], wa.y);
                    fma2(acc[1][1], d[s + 1], wa.y);
                    fma2(acc[1][2], d[s + 2], wa.y);
                    fma2(acc[1][3], d[s + 3], wa.y);
                    fma2(acc[2][0], d[s + 0], wb.x);
                    fma2(acc[2][1], d[s + 1], wb.x);
                    fma2(acc[2][2], d[s + 2], wb.x);
                    fma2(acc[2][3], d[s + 3], wb.x);
                    fma2(acc[3][0], d[s + 0], wb.y);
                    fma2(acc[3][1], d[s + 1], wb.y);
                    fma2(acc[3][2], d[s + 2], wb.y);
                    fma2(acc[3][3], d[s + 3], wb.y);
                }
            }
        }
    }
    size_t ob = (size_t)(z + 1) * PPl + (y + 1) * PX + (x0 + 4);
    #pragma unroll
    for (int p = 0; p < 4; p++) {
        float2 v0 = upk(acc[p][0]), v1 = upk(acc[p][1]);
        float2 v2 = upk(acc[p][2]), v3 = upk(acc[p][3]);
        float4 lo = make_float4(fmaxf(v0.x, 0.f), fmaxf(v1.x, 0.f), fmaxf(v2.x, 0.f), fmaxf(v3.x, 0.f));
        float4 hi = make_float4(fmaxf(v0.y, 0.f), fmaxf(v1.y, 0.f), fmaxf(v2.y, 0.f), fmaxf(v3.y, 0.f));
        *reinterpret_cast<float4*>(&g_hp[(size_t)(2 * p)     * PV + ob]) = lo;
        *reinterpret_cast<float4*>(&g_hp[(size_t)(2 * p + 1) * PV + ob]) = hi;
    }
}

// ---------------------------------------------------------------------------
// conv2 (R10 structure: direct LDG inputs, no staging/syncs) + 48B-padded
// weight taps (2x LDS.128 + LDS.64 per s). 8->27 oc, grid.z = group of 9.
// ---------------------------------------------------------------------------
__global__ __launch_bounds__(256, 3) void k_conv2(const float* __restrict__ w2)
{
    __shared__ float2 ws[8 * 27 * 6];   // [ic][tap][6] (slot 5 = pad), 48B/tap
    int tid  = threadIdx.y * 32 + threadIdx.x;
    int base = blockIdx.z * 9;
    for (int i = tid; i < 8 * 27 * 5; i += 256) {
        int p = i % 5; int it = i / 5; int t = it % 27; int ic = it / 27;
        float wlo = w2[((base + 2 * p) * 8 + ic) * 27 + t];
        float whi = (2 * p + 1 < 9) ? w2[((base + 2 * p + 1) * 8 + ic) * 27 + t] : 0.f;
        ws[it * 6 + p] = make_float2(wlo, whi);
    }
    __syncthreads();

    int x0 = threadIdx.x * 4;
    int y  = blockIdx.x * 8 + threadIdx.y;
    int z  = blockIdx.y;

    u64 acc[5][4];   // [ocpair][x]
    #pragma unroll
    for (int p = 0; p < 5; p++) { acc[p][0] = 0; acc[p][1] = 0; acc[p][2] = 0; acc[p][3] = 0; }

    #pragma unroll 1
    for (int ic = 0; ic < 8; ic++) {
        const float* xc = g_hp + (size_t)ic * PV + (size_t)z * PPl + y * PX + x0 + 3;
        #pragma unroll
        for (int dz = 0; dz < 3; dz++) {
            #pragma unroll
            for (int dy = 0; dy < 3; dy++) {
                const float* r = xc + dz * PPl + dy * PX;
                float  i0 = r[0];
                float4 a4 = *reinterpret_cast<const float4*>(r + 1);
                float  i5 = r[5];
                u64 d[6];
                d[0] = pk(i0,   i0);   d[1] = pk(a4.x, a4.x);
                d[2] = pk(a4.y, a4.y); d[3] = pk(a4.z, a4.z);
                d[4] = pk(a4.w, a4.w); d[5] = pk(i5,   i5);
                int tap0 = ic * 27 + (dz * 3 + dy) * 3;
                #pragma unroll
                for (int s = 0; s < 3; s++) {
                    const float2* wb = &ws[(tap0 + s) * 6];
                    ulonglong2 w01 = *reinterpret_cast<const ulonglong2*>(wb);
                    ulonglong2 w23 = *reinterpret_cast<const ulonglong2*>(wb + 2);
                    u64        w4  = *reinterpret_cast<const u64*>(wb + 4);
                    fma2(acc[0][0], d[s + 0], w01.x);
                    fma2(acc[0][1], d[s + 1], w01.x);
                    fma2(acc[0][2], d[s + 2], w01.x);
                    fma2(acc[0][3], d[s + 3], w01.x);
                    fma2(acc[1][0], d[s + 0], w01.y);
                    fma2(acc[1][1], d[s + 1], w01.y);
                    fma2(acc[1][2], d[s + 2], w01.y);
                    fma2(acc[1][3], d[s + 3], w01.y);
                    fma2(acc[2][0], d[s + 0], w23.x);
                    fma2(acc[2][1], d[s + 1], w23.x);
                    fma2(acc[2][2], d[s + 2], w23.x);
                    fma2(acc[2][3], d[s + 3], w23.x);
                    fma2(acc[3][0], d[s + 0], w23.y);
                    fma2(acc[3][1], d[s + 1], w23.y);
                    fma2(acc[3][2], d[s + 2], w23.y);
                    fma2(acc[3][3], d[s + 3], w23.y);
                    fma2(acc[4][0], d[s + 0], w4);
                    fma2(acc[4][1], d[s + 1], w4);
                    fma2(acc[4][2], d[s + 2], w4);
                    fma2(acc[4][3], d[s + 3], w4);
                }
            }
        }
    }
    size_t ob = (size_t)z * Pl + y * 128 + x0;
    #pragma unroll
    for (int o = 0; o < 9; o++) {
        int p = o >> 1, h = o & 1;
        float2 v0 = upk(acc[p][0]), v1 = upk(acc[p][1]);
        float2 v2 = upk(acc[p][2]), v3 = upk(acc[p][3]);
        float4 f = h ? make_float4(v0.y, v1.y, v2.y, v3.y)
                     : make_float4(v0.x, v1.x, v2.x, v3.x);
        *reinterpret_cast<float4*>(&g_w[(size_t)(base + o) * V + ob]) = f;
    }
}

// ---------------------------------------------------------------------------
// adaptive conv (proven R5 version): width 4, all 8 channels, fused L1 norm.
// ---------------------------------------------------------------------------
__global__ __launch_bounds__(256) void k_adapt(float* __restrict__ dout,
                                               int src, int dst)
{
    const float* in = (src == 0) ? g_xp : (src == 1 ? g_tp : g_hp);

    int x0 = threadIdx.x * 4;
    int y  = blockIdx.x * 8 + threadIdx.y;
    int z  = blockIdx.y;
    size_t ob  = (size_t)z * Pl + y * 128 + x0;
    size_t ibp = (size_t)z * PPl + y * PX + x0 + 3;

    u64 acc[8][2];
    #pragma unroll
    for (int c = 0; c < 8; c++) { acc[c][0] = 0; acc[c][1] = 0; }
    u64 nrm[2] = {0, 0};

    #pragma unroll
    for (int dz = 0; dz < 3; dz++) {
        #pragma unroll
        for (int dy = 0; dy < 3; dy++) {
            u64 q[3][2];
            #pragma unroll
            for (int s = 0; s < 3; s++) {
                const float* wr = g_w + (size_t)(dz * 9 + dy * 3 + s) * V + ob;
                float4 w0 = *reinterpret_cast<const float4*>(wr);
                q[s][0] = pk(w0.x, w0.y); q[s][1] = pk(w0.z, w0.w);
                nrm[0] = add2(nrm[0], abs2(q[s][0]));
                nrm[1] = add2(nrm[1], abs2(q[s][1]));
            }
            #pragma unroll
            for (int c = 0; c < 8; c++) {
                const float* r = in + (size_t)c * PV + ibp + dz * PPl + dy * PX;
                float  i0 = r[0];
                float4 a4 = *reinterpret_cast<const float4*>(r + 1);
                float  i5 = r[5];
                float iv[6] = {i0, a4.x, a4.y, a4.z, a4.w, i5};
                u64 p[5];
                #pragma unroll
                for (int k = 0; k < 5; k++) p[k] = pk(iv[k], iv[k + 1]);
                #pragma unroll
                for (int s = 0; s < 3; s++) {
                    fma2(acc[c][0], p[s + 0], q[s][0]);
                    fma2(acc[c][1], p[s + 2], q[s][1]);
                }
            }
        }
    }

    u64 rn[2];
    #pragma unroll
    for (int j = 0; j < 2; j++) {
        float2 n2 = upk(nrm[j]);
        rn[j] = pk(1.f / fmaxf(n2.x, 1e-12f), 1.f / fmaxf(n2.y, 1e-12f));
    }

    if (dst == 0) {
        #pragma unroll
        for (int c = 0; c < 8; c++) {
            float2 v0 = upk(mul2(acc[c][0], rn[0]));
            float2 v1 = upk(mul2(acc[c][1], rn[1]));
            *reinterpret_cast<float4*>(&dout[(size_t)c * V + ob]) =
                make_float4(v0.x, v0.y, v1.x, v1.y);
        }
    } else {
        float* out = (dst == 1) ? g_tp : g_hp;
        size_t op = (size_t)(z + 1) * PPl + (y + 1) * PX + (x0 + 4);
        #pragma unroll
        for (int c = 0; c < 8; c++) {
            float2 v0 = upk(mul2(acc[c][0], rn[0]));
            float2 v1 = upk(mul2(acc[c][1], rn[1]));
            *reinterpret_cast<float4*>(&out[(size_t)c * PV + op]) =
                make_float4(v0.x, v0.y, v1.x, v1.y);
        }
    }
}

// ---------------------------------------------------------------------------
extern "C" void kernel_launch(void* const* d_in, const int* in_sizes, int n_in,
                              void* d_out, int out_size)
{
    const float* x  = (const float*)d_in[0];
    const float* w1 = (n_in > 1) ? (const float*)d_in[1] : nullptr;
    const float* b1 = (n_in > 2) ? (const float*)d_in[2] : nullptr;
    const float* w2 = (n_in > 3) ? (const float*)d_in[3] : nullptr;
    for (int i = 0; i < n_in; i++) {
        switch (in_sizes[i]) {
            case 8 * V: x  = (const float*)d_in[i]; break;
            case 1728:  w1 = (const float*)d_in[i]; break;
            case 8:     b1 = (const float*)d_in[i]; break;
            case 5832:  w2 = (const float*)d_in[i]; break;
            default: break;
        }
    }

    int nrow = 8 * 130 * 130;
    dim3 cblk(32, 8);
    dim3 cg(16, 128);

    // Profiled launch is #4 -> k_conv1 sits there this round.
    k_pad_x<<<nrow, 160>>>(x);                   // 1
    k_halo_h<<<nrow, 160>>>();                   // 2
    k_halo_t<<<nrow, 160>>>();                   // 3
    k_conv1<<<cg, cblk>>>(w1, b1);               // 4  <-- profiled
    k_conv2<<<dim3(16, 128, 3), cblk>>>(w2);     // 5
    float* out = (float*)d_out;
    dim3 ablk(32, 8);
    k_adapt<<<cg, ablk>>>(out, 0, 1);            // 6: g_xp -> g_tp
    k_adapt<<<cg, ablk>>>(out, 1, 2);            // 7: g_tp -> g_hp
    k_adapt<<<cg, ablk>>>(out, 2, 0);            // 8: g_hp -> d_out
}

// round 14
// speedup vs baseline: 1.0626x; 1.0626x over previous
#include <cuda_runtime.h>

#define Pl  (128*128)
#define V   (128*128*128)
#define PX  136
#define PPl (130*136)
#define PV  (130*130*136)

typedef unsigned long long u64;

__device__ __forceinline__ u64 pk(float lo, float hi) {
    u64 r; asm("mov.b64 %0,{%1,%2};" : "=l"(r) : "f"(lo), "f"(hi)); return r;
}
__device__ __forceinline__ void fma2(u64 &d, u64 a, u64 b) {
    asm("fma.rn.f32x2 %0,%1,%2,%0;" : "+l"(d) : "l"(a), "l"(b));
}
__device__ __forceinline__ u64 mul2(u64 a, u64 b) {
    u64 r; asm("mul.rn.f32x2 %0,%1,%2;" : "=l"(r) : "l"(a), "l"(b)); return r;
}
__device__ __forceinline__ u64 add2(u64 a, u64 b) {
    u64 r; asm("add.rn.f32x2 %0,%1,%2;" : "=l"(r) : "l"(a), "l"(b)); return r;
}
__device__ __forceinline__ u64 abs2(u64 a) { return a & 0x7FFFFFFF7FFFFFFFULL; }
__device__ __forceinline__ float2 upk(u64 a) {
    float2 f; asm("mov.b64 {%0,%1},%2;" : "=f"(f.x), "=f"(f.y) : "l"(a)); return f;
}

// Padded scratch: [8][130][130][136], data voxel (z,y,x) at (z+1, y+1, x+4).
__device__ float g_xp[8 * PV];
__device__ float g_hp[8 * PV];
__device__ float g_tp[8 * PV];
__device__ float g_w [27 * V];   // unnormalized conv2 output (flat)

// ---------------------------------------------------------------------------
// pad_x: copy x into g_xp interior, zero g_xp halo
// ---------------------------------------------------------------------------
__global__ __launch_bounds__(160) void k_pad_x(const float* __restrict__ x)
{
    int row = blockIdx.x;                 // 8*130*130 rows
    int xx  = threadIdx.x;
    if (xx >= PX) return;
    int c   = row / (130 * 130);
    int rem = row % (130 * 130);
    int zz  = rem / 130;
    int yy  = rem % 130;
    bool halo = (zz == 0) | (zz == 129) | (yy == 0) | (yy == 129) | (xx < 4) | (xx >= 132);
    float v = 0.f;
    if (!halo)
        v = x[(size_t)c * V + (size_t)(zz - 1) * Pl + (yy - 1) * 128 + (xx - 4)];
    g_xp[(size_t)c * PV + zz * PPl + yy * PX + xx] = v;
}

// ---------------------------------------------------------------------------
// pad_halos: zero halos of g_hp and g_tp
// ---------------------------------------------------------------------------
__global__ __launch_bounds__(160) void k_pad_halos()
{
    int row = blockIdx.x;
    int xx  = threadIdx.x;
    if (xx >= PX) return;
    int c   = row / (130 * 130);
    int rem = row % (130 * 130);
    int zz  = rem / 130;
    int yy  = rem % 130;
    bool halo = (zz == 0) | (zz == 129) | (yy == 0) | (yy == 129) | (xx < 4) | (xx >= 132);
    if (halo) {
        size_t po = (size_t)c * PV + zz * PPl + yy * PX + xx;
        g_hp[po] = 0.f;
        g_tp[po] = 0.f;
    }
}

// ---------------------------------------------------------------------------
// conv1 (R13, measured 134.7us): oc-pair lanes, LDS.128 weight loads.
// ---------------------------------------------------------------------------
__global__ __launch_bounds__(256, 4) void k_conv1(const float* __restrict__ w1,
                                                  const float* __restrict__ b1)
{
    __shared__ float2 ws[8 * 27 * 4];   // [ic][tap][pair], tap group = 32B aligned
    __shared__ float2 bs[4];
    int tid = threadIdx.y * 32 + threadIdx.x;
    for (int i = tid; i < 864; i += 256) {
        int p = i & 3; int it = i >> 2; int t = it % 27; int ic = it / 27;
        ws[i] = make_float2(w1[(2 * p) * 216 + ic * 27 + t],
                            w1[(2 * p + 1) * 216 + ic * 27 + t]);
    }
    if (tid < 4) bs[tid] = make_float2(b1[2 * tid], b1[2 * tid + 1]);
    __syncthreads();

    int x0 = threadIdx.x * 4;
    int y  = blockIdx.x * 8 + threadIdx.y;
    int z  = blockIdx.y;

    u64 acc[4][4];   // [ocpair][x]
    #pragma unroll
    for (int p = 0; p < 4; p++) {
        u64 b = *reinterpret_cast<const u64*>(&bs[p]);
        acc[p][0] = b; acc[p][1] = b; acc[p][2] = b; acc[p][3] = b;
    }

    #pragma unroll 1
    for (int ic = 0; ic < 8; ic++) {
        const float* xc = g_xp + (size_t)ic * PV + (size_t)z * PPl + y * PX + x0 + 3;
        #pragma unroll
        for (int dz = 0; dz < 3; dz++) {
            #pragma unroll
            for (int dy = 0; dy < 3; dy++) {
                const float* r = xc + dz * PPl + dy * PX;
                float  i0 = r[0];
                float4 a4 = *reinterpret_cast<const float4*>(r + 1);
                float  i5 = r[5];
                u64 d[6];
                d[0] = pk(i0,   i0);   d[1] = pk(a4.x, a4.x);
                d[2] = pk(a4.y, a4.y); d[3] = pk(a4.z, a4.z);
                d[4] = pk(a4.w, a4.w); d[5] = pk(i5,   i5);
                const ulonglong2* wq2 =
                    reinterpret_cast<const ulonglong2*>(&ws[(ic * 27 + (dz * 3 + dy) * 3) * 4]);
                #pragma unroll
                for (int s = 0; s < 3; s++) {
                    ulonglong2 wa = wq2[2 * s];
                    ulonglong2 wb = wq2[2 * s + 1];
                    fma2(acc[0][0], d[s + 0], wa.x);
                    fma2(acc[0][1], d[s + 1], wa.x);
                    fma2(acc[0][2], d[s + 2], wa.x);
                    fma2(acc[0][3], d[s + 3], wa.x);
                    fma2(acc[1][0], d[s + 0], wa.y);
                    fma2(acc[1][1], d[s + 1], wa.y);
                    fma2(acc[1][2], d[s + 2], wa.y);
                    fma2(acc[1][3], d[s + 3], wa.y);
                    fma2(acc[2][0], d[s + 0], wb.x);
                    fma2(acc[2][1], d[s + 1], wb.x);
                    fma2(acc[2][2], d[s + 2], wb.x);
                    fma2(acc[2][3], d[s + 3], wb.x);
                    fma2(acc[3][0], d[s + 0], wb.y);
                    fma2(acc[3][1], d[s + 1], wb.y);
                    fma2(acc[3][2], d[s + 2], wb.y);
                    fma2(acc[3][3], d[s + 3], wb.y);
                }
            }
        }
    }
    size_t ob = (size_t)(z + 1) * PPl + (y + 1) * PX + (x0 + 4);
    #pragma unroll
    for (int p = 0; p < 4; p++) {
        float2 v0 = upk(acc[p][0]), v1 = upk(acc[p][1]);
        float2 v2 = upk(acc[p][2]), v3 = upk(acc[p][3]);
        float4 lo = make_float4(fmaxf(v0.x, 0.f), fmaxf(v1.x, 0.f), fmaxf(v2.x, 0.f), fmaxf(v3.x, 0.f));
        float4 hi = make_float4(fmaxf(v0.y, 0.f), fmaxf(v1.y, 0.f), fmaxf(v2.y, 0.f), fmaxf(v3.y, 0.f));
        *reinterpret_cast<float4*>(&g_hp[(size_t)(2 * p)     * PV + ob]) = lo;
        *reinterpret_cast<float4*>(&g_hp[(size_t)(2 * p + 1) * PV + ob]) = hi;
    }
}

// ---------------------------------------------------------------------------
// conv2 (EXACT R10 revert, measured 469us / fma 72.9%): direct LDG inputs,
// 5-slot weight smem, plain u64 weight loads. 8->27 oc, grid.z = group of 9.
// ---------------------------------------------------------------------------
__global__ __launch_bounds__(256, 3) void k_conv2(const float* __restrict__ w2)
{
    __shared__ float2 ws[8 * 27 * 5];   // [ic][tap][pair]
    int tid = threadIdx.y * 32 + threadIdx.x;
    int base = blockIdx.z * 9;
    for (int i = tid; i < 8 * 27 * 5; i += 256) {
        int p = i % 5; int it = i / 5; int t = it % 27; int ic = it / 27;
        float wlo = w2[((base + 2 * p) * 8 + ic) * 27 + t];
        float whi = (2 * p + 1 < 9) ? w2[((base + 2 * p + 1) * 8 + ic) * 27 + t] : 0.f;
        ws[i] = make_float2(wlo, whi);
    }
    __syncthreads();

    int x0 = threadIdx.x * 4;
    int y  = blockIdx.x * 8 + threadIdx.y;
    int z  = blockIdx.y;

    u64 acc[5][4];   // [ocpair][x]
    #pragma unroll
    for (int p = 0; p < 5; p++) { acc[p][0] = 0; acc[p][1] = 0; acc[p][2] = 0; acc[p][3] = 0; }

    #pragma unroll 1
    for (int ic = 0; ic < 8; ic++) {
        const float* xc = g_hp + (size_t)ic * PV + (size_t)z * PPl + y * PX + x0 + 3;
        #pragma unroll
        for (int dz = 0; dz < 3; dz++) {
            #pragma unroll
            for (int dy = 0; dy < 3; dy++) {
                const float* r = xc + dz * PPl + dy * PX;
                float  i0 = r[0];
                float4 a4 = *reinterpret_cast<const float4*>(r + 1);
                float  i5 = r[5];
                u64 d[6];
                d[0] = pk(i0,   i0);   d[1] = pk(a4.x, a4.x);
                d[2] = pk(a4.y, a4.y); d[3] = pk(a4.z, a4.z);
                d[4] = pk(a4.w, a4.w); d[5] = pk(i5,   i5);
                const u64* wq = reinterpret_cast<const u64*>(&ws[(ic * 27 + (dz * 3 + dy) * 3) * 5]);
                #pragma unroll
                for (int s = 0; s < 3; s++) {
                    #pragma unroll
                    for (int p = 0; p < 5; p++) {
                        u64 w = wq[s * 5 + p];
                        fma2(acc[p][0], d[s + 0], w);
                        fma2(acc[p][1], d[s + 1], w);
                        fma2(acc[p][2], d[s + 2], w);
                        fma2(acc[p][3], d[s + 3], w);
                    }
                }
            }
        }
    }
    size_t ob = (size_t)z * Pl + y * 128 + x0;
    #pragma unroll
    for (int o = 0; o < 9; o++) {
        int p = o >> 1, h = o & 1;
        float2 v0 = upk(acc[p][0]), v1 = upk(acc[p][1]);
        float2 v2 = upk(acc[p][2]), v3 = upk(acc[p][3]);
        float4 f = h ? make_float4(v0.y, v1.y, v2.y, v3.y)
                     : make_float4(v0.x, v1.x, v2.x, v3.x);
        *reinterpret_cast<float4*>(&g_w[(size_t)(base + o) * V + ob]) = f;
    }
}

// ---------------------------------------------------------------------------
// adaptive conv: width 4, all 8 channels, fused L1 norm. (256,3) caps regs
// at 85 -> 3 CTAs/SM (occ 33% vs 22%) for more memory-level parallelism.
// ---------------------------------------------------------------------------
__global__ __launch_bounds__(256, 3) void k_adapt(float* __restrict__ dout,
                                                  int src, int dst)
{
    const float* in = (src == 0) ? g_xp : (src == 1 ? g_tp : g_hp);

    int x0 = threadIdx.x * 4;
    int y  = blockIdx.x * 8 + threadIdx.y;
    int z  = blockIdx.y;
    size_t ob  = (size_t)z * Pl + y * 128 + x0;
    size_t ibp = (size_t)z * PPl + y * PX + x0 + 3;

    u64 acc[8][2];
    #pragma unroll
    for (int c = 0; c < 8; c++) { acc[c][0] = 0; acc[c][1] = 0; }
    u64 nrm[2] = {0, 0};

    #pragma unroll
    for (int dz = 0; dz < 3; dz++) {
        #pragma unroll
        for (int dy = 0; dy < 3; dy++) {
            u64 q[3][2];
            #pragma unroll
            for (int s = 0; s < 3; s++) {
                const float* wr = g_w + (size_t)(dz * 9 + dy * 3 + s) * V + ob;
                float4 w0 = *reinterpret_cast<const float4*>(wr);
                q[s][0] = pk(w0.x, w0.y); q[s][1] = pk(w0.z, w0.w);
                nrm[0] = add2(nrm[0], abs2(q[s][0]));
                nrm[1] = add2(nrm[1], abs2(q[s][1]));
            }
            #pragma unroll
            for (int c = 0; c < 8; c++) {
                const float* r = in + (size_t)c * PV + ibp + dz * PPl + dy * PX;
                float  i0 = r[0];
                float4 a4 = *reinterpret_cast<const float4*>(r + 1);
                float  i5 = r[5];
                float iv[6] = {i0, a4.x, a4.y, a4.z, a4.w, i5};
                u64 p[5];
                #pragma unroll
                for (int k = 0; k < 5; k++) p[k] = pk(iv[k], iv[k + 1]);
                #pragma unroll
                for (int s = 0; s < 3; s++) {
                    fma2(acc[c][0], p[s + 0], q[s][0]);
                    fma2(acc[c][1], p[s + 2], q[s][1]);
                }
            }
        }
    }

    u64 rn[2];
    #pragma unroll
    for (int j = 0; j < 2; j++) {
        float2 n2 = upk(nrm[j]);
        rn[j] = pk(1.f / fmaxf(n2.x, 1e-12f), 1.f / fmaxf(n2.y, 1e-12f));
    }

    if (dst == 0) {
        #pragma unroll
        for (int c = 0; c < 8; c++) {
            float2 v0 = upk(mul2(acc[c][0], rn[0]));
            float2 v1 = upk(mul2(acc[c][1], rn[1]));
            *reinterpret_cast<float4*>(&dout[(size_t)c * V + ob]) =
                make_float4(v0.x, v0.y, v1.x, v1.y);
        }
    } else {
        float* out = (dst == 1) ? g_tp : g_hp;
        size_t op = (size_t)(z + 1) * PPl + (y + 1) * PX + (x0 + 4);
        #pragma unroll
        for (int c = 0; c < 8; c++) {
            float2 v0 = upk(mul2(acc[c][0], rn[0]));
            float2 v1 = upk(mul2(acc[c][1], rn[1]));
            *reinterpret_cast<float4*>(&out[(size_t)c * PV + op]) =
                make_float4(v0.x, v0.y, v1.x, v1.y);
        }
    }
}

// ---------------------------------------------------------------------------
extern "C" void kernel_launch(void* const* d_in, const int* in_sizes, int n_in,
                              void* d_out, int out_size)
{
    const float* x  = (const float*)d_in[0];
    const float* w1 = (n_in > 1) ? (const float*)d_in[1] : nullptr;
    const float* b1 = (n_in > 2) ? (const float*)d_in[2] : nullptr;
    const float* w2 = (n_in > 3) ? (const float*)d_in[3] : nullptr;
    for (int i = 0; i < n_in; i++) {
        switch (in_sizes[i]) {
            case 8 * V: x  = (const float*)d_in[i]; break;
            case 1728:  w1 = (const float*)d_in[i]; break;
            case 8:     b1 = (const float*)d_in[i]; break;
            case 5832:  w2 = (const float*)d_in[i]; break;
            default: break;
        }
    }

    int nrow = 8 * 130 * 130;
    dim3 cblk(32, 8);
    dim3 cg(16, 128);

    // Profiled launch is #4 -> k_conv2 sits there (verify the revert).
    k_pad_x<<<nrow, 160>>>(x);                   // 1
    k_conv1<<<cg, cblk>>>(w1, b1);               // 2
    k_pad_halos<<<nrow, 160>>>();                // 3
    k_conv2<<<dim3(16, 128, 3), cblk>>>(w2);     // 4  <-- profiled
    float* out = (float*)d_out;
    dim3 ablk(32, 8);
    k_adapt<<<cg, ablk>>>(out, 0, 1);            // 5: g_xp -> g_tp
    k_adapt<<<cg, ablk>>>(out, 1, 2);            // 6: g_tp -> g_hp
    k_adapt<<<cg, ablk>>>(out, 2, 0);            // 7: g_hp -> d_out
}

// round 16
// speedup vs baseline: 1.1815x; 1.1118x over previous
#include <cuda_runtime.h>

#define Pl  (128*128)
#define V   (128*128*128)
#define PX  136
#define PPl (130*136)
#define PV  (130*130*136)

typedef unsigned long long u64;

__device__ __forceinline__ u64 pk(float lo, float hi) {
    u64 r; asm("mov.b64 %0,{%1,%2};" : "=l"(r) : "f"(lo), "f"(hi)); return r;
}
__device__ __forceinline__ void fma2(u64 &d, u64 a, u64 b) {
    asm("fma.rn.f32x2 %0,%1,%2,%0;" : "+l"(d) : "l"(a), "l"(b));
}
__device__ __forceinline__ u64 mul2(u64 a, u64 b) {
    u64 r; asm("mul.rn.f32x2 %0,%1,%2;" : "=l"(r) : "l"(a), "l"(b)); return r;
}
__device__ __forceinline__ u64 add2(u64 a, u64 b) {
    u64 r; asm("add.rn.f32x2 %0,%1,%2;" : "=l"(r) : "l"(a), "l"(b)); return r;
}
__device__ __forceinline__ u64 abs2(u64 a) { return a & 0x7FFFFFFF7FFFFFFFULL; }
__device__ __forceinline__ float2 upk(u64 a) {
    float2 f; asm("mov.b64 {%0,%1},%2;" : "=f"(f.x), "=f"(f.y) : "l"(a)); return f;
}

// Padded scratch: [8][130][130][136], data voxel (z,y,x) at (z+1, y+1, x+4).
// __device__ globals are zero-initialized; halos are NEVER written non-zero by
// any kernel, so no halo-zeroing launches are needed.
__device__ float g_xp[8 * PV];
__device__ float g_hp[8 * PV];
__device__ float g_tp[8 * PV];
__device__ float g_w [27 * V];   // unnormalized conv2 output (flat)

// ---------------------------------------------------------------------------
// pad_x: copy x interior into g_xp (float4 per thread; halo stays zero-init)
// ---------------------------------------------------------------------------
__global__ __launch_bounds__(256) void k_pad_x(const float* __restrict__ x)
{
    int i = blockIdx.x * 256 + threadIdx.x;      // 8*128*128*32 float4s
    int x4  = i & 31;
    int r   = i >> 5;                            // (c, z, y)
    int y   = r & 127;
    int zc  = r >> 7;
    int z   = zc & 127;
    int c   = zc >> 7;
    float4 v = *reinterpret_cast<const float4*>(x + (size_t)r * 128 + x4 * 4);
    *reinterpret_cast<float4*>(
        &g_xp[(size_t)c * PV + (size_t)(z + 1) * PPl + (y + 1) * PX + (x4 * 4 + 4)]) = v;
}

// ---------------------------------------------------------------------------
// conv1 (R13, measured 134.7us): oc-pair lanes, LDS.128 weight loads.
// ---------------------------------------------------------------------------
__global__ __launch_bounds__(256, 4) void k_conv1(const float* __restrict__ w1,
                                                  const float* __restrict__ b1)
{
    __shared__ float2 ws[8 * 27 * 4];   // [ic][tap][pair], tap group = 32B aligned
    __shared__ float2 bs[4];
    int tid = threadIdx.y * 32 + threadIdx.x;
    for (int i = tid; i < 864; i += 256) {
        int p = i & 3; int it = i >> 2; int t = it % 27; int ic = it / 27;
        ws[i] = make_float2(w1[(2 * p) * 216 + ic * 27 + t],
                            w1[(2 * p + 1) * 216 + ic * 27 + t]);
    }
    if (tid < 4) bs[tid] = make_float2(b1[2 * tid], b1[2 * tid + 1]);
    __syncthreads();

    int x0 = threadIdx.x * 4;
    int y  = blockIdx.x * 8 + threadIdx.y;
    int z  = blockIdx.y;

    u64 acc[4][4];   // [ocpair][x]
    #pragma unroll
    for (int p = 0; p < 4; p++) {
        u64 b = *reinterpret_cast<const u64*>(&bs[p]);
        acc[p][0] = b; acc[p][1] = b; acc[p][2] = b; acc[p][3] = b;
    }

    #pragma unroll 1
    for (int ic = 0; ic < 8; ic++) {
        const float* xc = g_xp + (size_t)ic * PV + (size_t)z * PPl + y * PX + x0 + 3;
        #pragma unroll
        for (int dz = 0; dz < 3; dz++) {
            #pragma unroll
            for (int dy = 0; dy < 3; dy++) {
                const float* r = xc + dz * PPl + dy * PX;
                float  i0 = r[0];
                float4 a4 = *reinterpret_cast<const float4*>(r + 1);
                float  i5 = r[5];
                u64 d[6];
                d[0] = pk(i0,   i0);   d[1] = pk(a4.x, a4.x);
                d[2] = pk(a4.y, a4.y); d[3] = pk(a4.z, a4.z);
                d[4] = pk(a4.w, a4.w); d[5] = pk(i5,   i5);
                const ulonglong2* wq2 =
                    reinterpret_cast<const ulonglong2*>(&ws[(ic * 27 + (dz * 3 + dy) * 3) * 4]);
                #pragma unroll
                for (int s = 0; s < 3; s++) {
                    ulonglong2 wa = wq2[2 * s];
                    ulonglong2 wb = wq2[2 * s + 1];
                    fma2(acc[0][0], d[s + 0], wa.x);
                    fma2(acc[0][1], d[s + 1], wa.x);
                    fma2(acc[0][2], d[s + 2], wa.x);
                    fma2(acc[0][3], d[s + 3], wa.x);
                    fma2(acc[1][0], d[s + 0], wa.y);
                    fma2(acc[1][1], d[s + 1], wa.y);
                    fma2(acc[1][2], d[s + 2], wa.y);
                    fma2(acc[1][3], d[s + 3], wa.y);
                    fma2(acc[2][0], d[s + 0], wb.x);
                    fma2(acc[2][1], d[s + 1], wb.x);
                    fma2(acc[2][2], d[s + 2], wb.x);
                    fma2(acc[2][3], d[s + 3], wb.x);
                    fma2(acc[3][0], d[s + 0], wb.y);
                    fma2(acc[3][1], d[s + 1], wb.y);
                    fma2(acc[3][2], d[s + 2], wb.y);
                    fma2(acc[3][3], d[s + 3], wb.y);
                }
            }
        }
    }
    size_t ob = (size_t)(z + 1) * PPl + (y + 1) * PX + (x0 + 4);
    #pragma unroll
    for (int p = 0; p < 4; p++) {
        float2 v0 = upk(acc[p][0]), v1 = upk(acc[p][1]);
        float2 v2 = upk(acc[p][2]), v3 = upk(acc[p][3]);
        float4 lo = make_float4(fmaxf(v0.x, 0.f), fmaxf(v1.x, 0.f), fmaxf(v2.x, 0.f), fmaxf(v3.x, 0.f));
        float4 hi = make_float4(fmaxf(v0.y, 0.f), fmaxf(v1.y, 0.f), fmaxf(v2.y, 0.f), fmaxf(v3.y, 0.f));
        *reinterpret_cast<float4*>(&g_hp[(size_t)(2 * p)     * PV + ob]) = lo;
        *reinterpret_cast<float4*>(&g_hp[(size_t)(2 * p + 1) * PV + ob]) = hi;
    }
}

// ---------------------------------------------------------------------------
// conv2 (R10/R14, measured 467.9us / fma 73.1%): direct LDG inputs, 5-slot
// weight smem, plain u64 weight loads. 8->27 oc, grid.z = group of 9.
// ---------------------------------------------------------------------------
__global__ __launch_bounds__(256, 3) void k_conv2(const float* __restrict__ w2)
{
    __shared__ float2 ws[8 * 27 * 5];   // [ic][tap][pair]
    int tid = threadIdx.y * 32 + threadIdx.x;
    int base = blockIdx.z * 9;
    for (int i = tid; i < 8 * 27 * 5; i += 256) {
        int p = i % 5; int it = i / 5; int t = it % 27; int ic = it / 27;
        float wlo = w2[((base + 2 * p) * 8 + ic) * 27 + t];
        float whi = (2 * p + 1 < 9) ? w2[((base + 2 * p + 1) * 8 + ic) * 27 + t] : 0.f;
        ws[i] = make_float2(wlo, whi);
    }
    __syncthreads();

    int x0 = threadIdx.x * 4;
    int y  = blockIdx.x * 8 + threadIdx.y;
    int z  = blockIdx.y;

    u64 acc[5][4];   // [ocpair][x]
    #pragma unroll
    for (int p = 0; p < 5; p++) { acc[p][0] = 0; acc[p][1] = 0; acc[p][2] = 0; acc[p][3] = 0; }

    #pragma unroll 1
    for (int ic = 0; ic < 8; ic++) {
        const float* xc = g_hp + (size_t)ic * PV + (size_t)z * PPl + y * PX + x0 + 3;
        #pragma unroll
        for (int dz = 0; dz < 3; dz++) {
            #pragma unroll
            for (int dy = 0; dy < 3; dy++) {
                const float* r = xc + dz * PPl + dy * PX;
                float  i0 = r[0];
                float4 a4 = *reinterpret_cast<const float4*>(r + 1);
                float  i5 = r[5];
                u64 d[6];
                d[0] = pk(i0,   i0);   d[1] = pk(a4.x, a4.x);
                d[2] = pk(a4.y, a4.y); d[3] = pk(a4.z, a4.z);
                d[4] = pk(a4.w, a4.w); d[5] = pk(i5,   i5);
                const u64* wq = reinterpret_cast<const u64*>(&ws[(ic * 27 + (dz * 3 + dy) * 3) * 5]);
                #pragma unroll
                for (int s = 0; s < 3; s++) {
                    #pragma unroll
                    for (int p = 0; p < 5; p++) {
                        u64 w = wq[s * 5 + p];
                        fma2(acc[p][0], d[s + 0], w);
                        fma2(acc[p][1], d[s + 1], w);
                        fma2(acc[p][2], d[s + 2], w);
                        fma2(acc[p][3], d[s + 3], w);
                    }
                }
            }
        }
    }
    size_t ob = (size_t)z * Pl + y * 128 + x0;
    #pragma unroll
    for (int o = 0; o < 9; o++) {
        int p = o >> 1, h = o & 1;
        float2 v0 = upk(acc[p][0]), v1 = upk(acc[p][1]);
        float2 v2 = upk(acc[p][2]), v3 = upk(acc[p][3]);
        float4 f = h ? make_float4(v0.y, v1.y, v2.y, v3.y)
                     : make_float4(v0.x, v1.x, v2.x, v3.x);
        *reinterpret_cast<float4*>(&g_w[(size_t)(base + o) * V + ob]) = f;
    }
}

// ---------------------------------------------------------------------------
// adaptive conv (EXACT R5, measured 102.8us): width 4, all 8 channels,
// fused L1 normalization, plain launch bounds (no reg cap -> no spills).
// ---------------------------------------------------------------------------
__global__ __launch_bounds__(256) void k_adapt(float* __restrict__ dout,
                                               int src, int dst)
{
    const float* in = (src == 0) ? g_xp : (src == 1 ? g_tp : g_hp);

    int x0 = threadIdx.x * 4;
    int y  = blockIdx.x * 8 + threadIdx.y;
    int z  = blockIdx.y;
    size_t ob  = (size_t)z * Pl + y * 128 + x0;
    size_t ibp = (size_t)z * PPl + y * PX + x0 + 3;

    u64 acc[8][2];
    #pragma unroll
    for (int c = 0; c < 8; c++) { acc[c][0] = 0; acc[c][1] = 0; }
    u64 nrm[2] = {0, 0};

    #pragma unroll
    for (int dz = 0; dz < 3; dz++) {
        #pragma unroll
        for (int dy = 0; dy < 3; dy++) {
            u64 q[3][2];
            #pragma unroll
            for (int s = 0; s < 3; s++) {
                const float* wr = g_w + (size_t)(dz * 9 + dy * 3 + s) * V + ob;
                float4 w0 = *reinterpret_cast<const float4*>(wr);
                q[s][0] = pk(w0.x, w0.y); q[s][1] = pk(w0.z, w0.w);
                nrm[0] = add2(nrm[0], abs2(q[s][0]));
                nrm[1] = add2(nrm[1], abs2(q[s][1]));
            }
            #pragma unroll
            for (int c = 0; c < 8; c++) {
                const float* r = in + (size_t)c * PV + ibp + dz * PPl + dy * PX;
                float  i0 = r[0];
                float4 a4 = *reinterpret_cast<const float4*>(r + 1);
                float  i5 = r[5];
                float iv[6] = {i0, a4.x, a4.y, a4.z, a4.w, i5};
                u64 p[5];
                #pragma unroll
                for (int k = 0; k < 5; k++) p[k] = pk(iv[k], iv[k + 1]);
                #pragma unroll
                for (int s = 0; s < 3; s++) {
                    fma2(acc[c][0], p[s + 0], q[s][0]);
                    fma2(acc[c][1], p[s + 2], q[s][1]);
                }
            }
        }
    }

    u64 rn[2];
    #pragma unroll
    for (int j = 0; j < 2; j++) {
        float2 n2 = upk(nrm[j]);
        rn[j] = pk(1.f / fmaxf(n2.x, 1e-12f), 1.f / fmaxf(n2.y, 1e-12f));
    }

    if (dst == 0) {
        #pragma unroll
        for (int c = 0; c < 8; c++) {
            float2 v0 = upk(mul2(acc[c][0], rn[0]));
            float2 v1 = upk(mul2(acc[c][1], rn[1]));
            *reinterpret_cast<float4*>(&dout[(size_t)c * V + ob]) =
                make_float4(v0.x, v0.y, v1.x, v1.y);
        }
    } else {
        float* out = (dst == 1) ? g_tp : g_hp;
        size_t op = (size_t)(z + 1) * PPl + (y + 1) * PX + (x0 + 4);
        #pragma unroll
        for (int c = 0; c < 8; c++) {
            float2 v0 = upk(mul2(acc[c][0], rn[0]));
            float2 v1 = upk(mul2(acc[c][1], rn[1]));
            *reinterpret_cast<float4*>(&out[(size_t)c * PV + op]) =
                make_float4(v0.x, v0.y, v1.x, v1.y);
        }
    }
}

// ---------------------------------------------------------------------------
extern "C" void kernel_launch(void* const* d_in, const int* in_sizes, int n_in,
                              void* d_out, int out_size)
{
    const float* x  = (const float*)d_in[0];
    const float* w1 = (n_in > 1) ? (const float*)d_in[1] : nullptr;
    const float* b1 = (n_in > 2) ? (const float*)d_in[2] : nullptr;
    const float* w2 = (n_in > 3) ? (const float*)d_in[3] : nullptr;
    for (int i = 0; i < n_in; i++) {
        switch (in_sizes[i]) {
            case 8 * V: x  = (const float*)d_in[i]; break;
            case 1728:  w1 = (const float*)d_in[i]; break;
            case 8:     b1 = (const float*)d_in[i]; break;
            case 5832:  w2 = (const float*)d_in[i]; break;
            default: break;
        }
    }

    dim3 cblk(32, 8);
    dim3 cg(16, 128);
    float* out = (float*)d_out;
    dim3 ablk(32, 8);

    // Profiled launch is #4 -> first k_adapt sits there this round.
    k_pad_x<<<8 * V / (4 * 256), 256>>>(x);      // 1 (interior only; halos stay 0)
    k_conv1<<<cg, cblk>>>(w1, b1);               // 2
    k_conv2<<<dim3(16, 128, 3), cblk>>>(w2);     // 3
    k_adapt<<<cg, ablk>>>(out, 0, 1);            // 4  <-- profiled: g_xp -> g_tp
    k_adapt<<<cg, ablk>>>(out, 1, 2);            // 5: g_tp -> g_hp
    k_adapt<<<cg, ablk>>>(out, 2, 0);            // 6: g_hp -> d_out
}

// round 17
// speedup vs baseline: 1.2521x; 1.0598x over previous
#include <cuda_runtime.h>

#define Pl  (128*128)
#define V   (128*128*128)
#define PX  136
#define PPl (130*136)
#define PV  (130*130*136)

typedef unsigned long long u64;

__device__ __forceinline__ u64 pk(float lo, float hi) {
    u64 r; asm("mov.b64 %0,{%1,%2};" : "=l"(r) : "f"(lo), "f"(hi)); return r;
}
__device__ __forceinline__ void fma2(u64 &d, u64 a, u64 b) {
    asm("fma.rn.f32x2 %0,%1,%2,%0;" : "+l"(d) : "l"(a), "l"(b));
}
__device__ __forceinline__ u64 mul2(u64 a, u64 b) {
    u64 r; asm("mul.rn.f32x2 %0,%1,%2;" : "=l"(r) : "l"(a), "l"(b)); return r;
}
__device__ __forceinline__ u64 add2(u64 a, u64 b) {
    u64 r; asm("add.rn.f32x2 %0,%1,%2;" : "=l"(r) : "l"(a), "l"(b)); return r;
}
__device__ __forceinline__ u64 abs2(u64 a) { return a & 0x7FFFFFFF7FFFFFFFULL; }
__device__ __forceinline__ float2 upk(u64 a) {
    float2 f; asm("mov.b64 {%0,%1},%2;" : "=f"(f.x), "=f"(f.y) : "l"(a)); return f;
}

// Padded scratch: [8][130][130][136], data voxel (z,y,x) at (z+1, y+1, x+4).
// __device__ globals are zero-initialized; halos are never written non-zero.
__device__ float g_xp[8 * PV];
__device__ float g_hp[8 * PV];
__device__ float g_tp[8 * PV];
__device__ float g_w [27 * V];   // unnormalized conv2 output (flat)

// ---------------------------------------------------------------------------
// pad_x halves: copy x interior into g_xp, 4 channels per launch
// ---------------------------------------------------------------------------
__global__ __launch_bounds__(256) void k_pad_x(const float* __restrict__ x, int c0)
{
    int i = blockIdx.x * 256 + threadIdx.x;      // 4*128*128*32 float4s
    int x4  = i & 31;
    int r   = i >> 5;                            // (c, z, y) within half
    int y   = r & 127;
    int zc  = r >> 7;
    int z   = zc & 127;
    int c   = (zc >> 7) + c0;
    float4 v = *reinterpret_cast<const float4*>(x + ((size_t)c * Pl * 128) + (size_t)z * Pl + y * 128 + x4 * 4);
    *reinterpret_cast<float4*>(
        &g_xp[(size_t)c * PV + (size_t)(z + 1) * PPl + (y + 1) * PX + (x4 * 4 + 4)]) = v;
}

// ---------------------------------------------------------------------------
// conv1 (R13, measured 134.7us): oc-pair lanes, LDS.128 weight loads.
// ---------------------------------------------------------------------------
__global__ __launch_bounds__(256, 4) void k_conv1(const float* __restrict__ w1,
                                                  const float* __restrict__ b1)
{
    __shared__ float2 ws[8 * 27 * 4];   // [ic][tap][pair], tap group = 32B aligned
    __shared__ float2 bs[4];
    int tid = threadIdx.y * 32 + threadIdx.x;
    for (int i = tid; i < 864; i += 256) {
        int p = i & 3; int it = i >> 2; int t = it % 27; int ic = it / 27;
        ws[i] = make_float2(w1[(2 * p) * 216 + ic * 27 + t],
                            w1[(2 * p + 1) * 216 + ic * 27 + t]);
    }
    if (tid < 4) bs[tid] = make_float2(b1[2 * tid], b1[2 * tid + 1]);
    __syncthreads();

    int x0 = threadIdx.x * 4;
    int y  = blockIdx.x * 8 + threadIdx.y;
    int z  = blockIdx.y;

    u64 acc[4][4];   // [ocpair][x]
    #pragma unroll
    for (int p = 0; p < 4; p++) {
        u64 b = *reinterpret_cast<const u64*>(&bs[p]);
        acc[p][0] = b; acc[p][1] = b; acc[p][2] = b; acc[p][3] = b;
    }

    #pragma unroll 1
    for (int ic = 0; ic < 8; ic++) {
        const float* xc = g_xp + (size_t)ic * PV + (size_t)z * PPl + y * PX + x0 + 3;
        #pragma unroll
        for (int dz = 0; dz < 3; dz++) {
            #pragma unroll
            for (int dy = 0; dy < 3; dy++) {
                const float* r = xc + dz * PPl + dy * PX;
                float  i0 = r[0];
                float4 a4 = *reinterpret_cast<const float4*>(r + 1);
                float  i5 = r[5];
                u64 d[6];
                d[0] = pk(i0,   i0);   d[1] = pk(a4.x, a4.x);
                d[2] = pk(a4.y, a4.y); d[3] = pk(a4.z, a4.z);
                d[4] = pk(a4.w, a4.w); d[5] = pk(i5,   i5);
                const ulonglong2* wq2 =
                    reinterpret_cast<const ulonglong2*>(&ws[(ic * 27 + (dz * 3 + dy) * 3) * 4]);
                #pragma unroll
                for (int s = 0; s < 3; s++) {
                    ulonglong2 wa = wq2[2 * s];
                    ulonglong2 wb = wq2[2 * s + 1];
                    fma2(acc[0][0], d[s + 0], wa.x);
                    fma2(acc[0][1], d[s + 1], wa.x);
                    fma2(acc[0][2], d[s + 2], wa.x);
                    fma2(acc[0][3], d[s + 3], wa.x);
                    fma2(acc[1][0], d[s + 0], wa.y);
                    fma2(acc[1][1], d[s + 1], wa.y);
                    fma2(acc[1][2], d[s + 2], wa.y);
                    fma2(acc[1][3], d[s + 3], wa.y);
                    fma2(acc[2][0], d[s + 0], wb.x);
                    fma2(acc[2][1], d[s + 1], wb.x);
                    fma2(acc[2][2], d[s + 2], wb.x);
                    fma2(acc[2][3], d[s + 3], wb.x);
                    fma2(acc[3][0], d[s + 0], wb.y);
                    fma2(acc[3][1], d[s + 1], wb.y);
                    fma2(acc[3][2], d[s + 2], wb.y);
                    fma2(acc[3][3], d[s + 3], wb.y);
                }
            }
        }
    }
    size_t ob = (size_t)(z + 1) * PPl + (y + 1) * PX + (x0 + 4);
    #pragma unroll
    for (int p = 0; p < 4; p++) {
        float2 v0 = upk(acc[p][0]), v1 = upk(acc[p][1]);
        float2 v2 = upk(acc[p][2]), v3 = upk(acc[p][3]);
        float4 lo = make_float4(fmaxf(v0.x, 0.f), fmaxf(v1.x, 0.f), fmaxf(v2.x, 0.f), fmaxf(v3.x, 0.f));
        float4 hi = make_float4(fmaxf(v0.y, 0.f), fmaxf(v1.y, 0.f), fmaxf(v2.y, 0.f), fmaxf(v3.y, 0.f));
        *reinterpret_cast<float4*>(&g_hp[(size_t)(2 * p)     * PV + ob]) = lo;
        *reinterpret_cast<float4*>(&g_hp[(size_t)(2 * p + 1) * PV + ob]) = hi;
    }
}

// ---------------------------------------------------------------------------
// conv2 v4: width 8 per thread (block 16x8=128 thr). Same oc-pair lanes and
// 5-slot weight smem as R10; per-row overhead amortized over 2x the FMAs
// (ratio 0.40 -> 0.24). acc = 40 u64; 40 independent FMA chains for ILP.
// ---------------------------------------------------------------------------
__global__ __launch_bounds__(128) void k_conv2(const float* __restrict__ w2)
{
    __shared__ float2 ws[8 * 27 * 5];   // [ic][tap][pair]
    int tid = threadIdx.y * 16 + threadIdx.x;
    int base = blockIdx.z * 9;
    for (int i = tid; i < 8 * 27 * 5; i += 128) {
        int p = i % 5; int it = i / 5; int t = it % 27; int ic = it / 27;
        float wlo = w2[((base + 2 * p) * 8 + ic) * 27 + t];
        float whi = (2 * p + 1 < 9) ? w2[((base + 2 * p + 1) * 8 + ic) * 27 + t] : 0.f;
        ws[i] = make_float2(wlo, whi);
    }
    __syncthreads();

    int x0 = threadIdx.x * 8;
    int y  = blockIdx.x * 8 + threadIdx.y;
    int z  = blockIdx.y;

    u64 acc[5][8];   // [ocpair][x]
    #pragma unroll
    for (int p = 0; p < 5; p++)
        #pragma unroll
        for (int xi = 0; xi < 8; xi++) acc[p][xi] = 0;

    #pragma unroll 1
    for (int ic = 0; ic < 8; ic++) {
        const float* xc = g_hp + (size_t)ic * PV + (size_t)z * PPl + y * PX + x0 + 3;
        #pragma unroll
        for (int dz = 0; dz < 3; dz++) {
            #pragma unroll
            for (int dy = 0; dy < 3; dy++) {
                const float* r = xc + dz * PPl + dy * PX;
                float  i0 = r[0];
                float4 a4 = *reinterpret_cast<const float4*>(r + 1);
                float4 b4 = *reinterpret_cast<const float4*>(r + 5);
                float  i9 = r[9];
                u64 d[10];
                d[0] = pk(i0,   i0);   d[1] = pk(a4.x, a4.x);
                d[2] = pk(a4.y, a4.y); d[3] = pk(a4.z, a4.z);
                d[4] = pk(a4.w, a4.w); d[5] = pk(b4.x, b4.x);
                d[6] = pk(b4.y, b4.y); d[7] = pk(b4.z, b4.z);
                d[8] = pk(b4.w, b4.w); d[9] = pk(i9,   i9);
                const u64* wq = reinterpret_cast<const u64*>(&ws[(ic * 27 + (dz * 3 + dy) * 3) * 5]);
                #pragma unroll
                for (int s = 0; s < 3; s++) {
                    #pragma unroll
                    for (int p = 0; p < 5; p++) {
                        u64 w = wq[s * 5 + p];
                        #pragma unroll
                        for (int xi = 0; xi < 8; xi++)
                            fma2(acc[p][xi], d[s + xi], w);
                    }
                }
            }
        }
    }
    size_t ob = (size_t)z * Pl + y * 128 + x0;
    #pragma unroll
    for (int o = 0; o < 9; o++) {
        int p = o >> 1, h = o & 1;
        float v[8];
        #pragma unroll
        for (int xi = 0; xi < 8; xi++) {
            float2 t = upk(acc[p][xi]);
            v[xi] = h ? t.y : t.x;
        }
        float* dst = &g_w[(size_t)(base + o) * V + ob];
        *reinterpret_cast<float4*>(dst)     = make_float4(v[0], v[1], v[2], v[3]);
        *reinterpret_cast<float4*>(dst + 4) = make_float4(v[4], v[5], v[6], v[7]);
    }
}

// ---------------------------------------------------------------------------
// adaptive conv (R5 code, 128-thread blocks): width 4, all 8 channels, fused
// L1 norm. 92 regs x 128 thr -> 5 CTAs/SM = 20 warps (vs 16) for more MLP.
// ---------------------------------------------------------------------------
__global__ __launch_bounds__(128) void k_adapt(float* __restrict__ dout,
                                               int src, int dst)
{
    const float* in = (src == 0) ? g_xp : (src == 1 ? g_tp : g_hp);

    int x0 = threadIdx.x * 4;               // 32 threads cover the x row
    int y  = blockIdx.x * 4 + threadIdx.y;  // 4 y per block
    int z  = blockIdx.y;
    size_t ob  = (size_t)z * Pl + y * 128 + x0;
    size_t ibp = (size_t)z * PPl + y * PX + x0 + 3;

    u64 acc[8][2];
    #pragma unroll
    for (int c = 0; c < 8; c++) { acc[c][0] = 0; acc[c][1] = 0; }
    u64 nrm[2] = {0, 0};

    #pragma unroll
    for (int dz = 0; dz < 3; dz++) {
        #pragma unroll
        for (int dy = 0; dy < 3; dy++) {
            u64 q[3][2];
            #pragma unroll
            for (int s = 0; s < 3; s++) {
                const float* wr = g_w + (size_t)(dz * 9 + dy * 3 + s) * V + ob;
                float4 w0 = *reinterpret_cast<const float4*>(wr);
                q[s][0] = pk(w0.x, w0.y); q[s][1] = pk(w0.z, w0.w);
                nrm[0] = add2(nrm[0], abs2(q[s][0]));
                nrm[1] = add2(nrm[1], abs2(q[s][1]));
            }
            #pragma unroll
            for (int c = 0; c < 8; c++) {
                const float* r = in + (size_t)c * PV + ibp + dz * PPl + dy * PX;
                float  i0 = r[0];
                float4 a4 = *reinterpret_cast<const float4*>(r + 1);
                float  i5 = r[5];
                float iv[6] = {i0, a4.x, a4.y, a4.z, a4.w, i5};
                u64 p[5];
                #pragma unroll
                for (int k = 0; k < 5; k++) p[k] = pk(iv[k], iv[k + 1]);
                #pragma unroll
                for (int s = 0; s < 3; s++) {
                    fma2(acc[c][0], p[s + 0], q[s][0]);
                    fma2(acc[c][1], p[s + 2], q[s][1]);
                }
            }
        }
    }

    u64 rn[2];
    #pragma unroll
    for (int j = 0; j < 2; j++) {
        float2 n2 = upk(nrm[j]);
        rn[j] = pk(1.f / fmaxf(n2.x, 1e-12f), 1.f / fmaxf(n2.y, 1e-12f));
    }

    if (dst == 0) {
        #pragma unroll
        for (int c = 0; c < 8; c++) {
            float2 v0 = upk(mul2(acc[c][0], rn[0]));
            float2 v1 = upk(mul2(acc[c][1], rn[1]));
            *reinterpret_cast<float4*>(&dout[(size_t)c * V + ob]) =
                make_float4(v0.x, v0.y, v1.x, v1.y);
        }
    } else {
        float* out = (dst == 1) ? g_tp : g_hp;
        size_t op = (size_t)(z + 1) * PPl + (y + 1) * PX + (x0 + 4);
        #pragma unroll
        for (int c = 0; c < 8; c++) {
            float2 v0 = upk(mul2(acc[c][0], rn[0]));
            float2 v1 = upk(mul2(acc[c][1], rn[1]));
            *reinterpret_cast<float4*>(&out[(size_t)c * PV + op]) =
                make_float4(v0.x, v0.y, v1.x, v1.y);
        }
    }
}

// ---------------------------------------------------------------------------
extern "C" void kernel_launch(void* const* d_in, const int* in_sizes, int n_in,
                              void* d_out, int out_size)
{
    const float* x  = (const float*)d_in[0];
    const float* w1 = (n_in > 1) ? (const float*)d_in[1] : nullptr;
    const float* b1 = (n_in > 2) ? (const float*)d_in[2] : nullptr;
    const float* w2 = (n_in > 3) ? (const float*)d_in[3] : nullptr;
    for (int i = 0; i < n_in; i++) {
        switch (in_sizes[i]) {
            case 8 * V: x  = (const float*)d_in[i]; break;
            case 1728:  w1 = (const float*)d_in[i]; break;
            case 8:     b1 = (const float*)d_in[i]; break;
            case 5832:  w2 = (const float*)d_in[i]; break;
            default: break;
        }
    }

    dim3 c1blk(32, 8);
    dim3 cg(16, 128);
    dim3 c2blk(16, 8);
    float* out = (float*)d_out;
    dim3 ablk(32, 4);
    dim3 ag(32, 128);

    int padBlocks = 4 * V / (4 * 256);
    // Profiled launch is #4 -> new k_conv2 sits there.
    k_pad_x<<<padBlocks, 256>>>(x, 0);           // 1 (channels 0-3)
    k_pad_x<<<padBlocks, 256>>>(x, 4);           // 2 (channels 4-7)
    k_conv1<<<cg, c1blk>>>(w1, b1);              // 3
    k_conv2<<<dim3(16, 128, 3), c2blk>>>(w2);    // 4  <-- profiled (width-8)
    k_adapt<<<ag, ablk>>>(out, 0, 1);            // 5: g_xp -> g_tp
    k_adapt<<<ag, ablk>>>(out, 1, 2);            // 6: g_tp -> g_hp
    k_adapt<<<ag, ablk>>>(out, 2, 0);            // 7: g_hp -> d_out
}